// round 12
// baseline (speedup 1.0000x reference)
#include <cuda_runtime.h>
#include <cuda_bf16.h>
#include <cuda_fp16.h>
#include <cstdint>

// CausalSelfAttention: B=4, T=4096, C=128, fp32 in/out.
// K1: tensorized QKV projection (mma.sync bf16 hi/lo x3-term; V as fp16 hi/lo).
// K2: persistent flash attention: warp-private 16-row tiles; S = bf16 3-term;
//     PV = fp16 2-term; software-pipelined fragment loads (reg double-buffer);
//     cp.async staged Q + double-buffered K/V; split-KV queue (CH=6);
//     fused per-tile combine.

#define BB 4
#define TT 4096
#define CC 128
#define BT (BB*TT)
#define QT_N 32
#define SCALE_L2E (0.08838834764831845f * 1.4426950408889634f)

#define BQ 128
#define BKT 64
#define CH 6
#define MAXSUB 11
#define NSLICES 748     // 4 * sum_qt ceil((2qt+2)/6)
#define NCTA 148

// ---------------- scratch (device globals; no cudaMalloc) -------------------
__device__ __align__(256) __nv_bfloat16 g_qh[BT*CC], g_ql[BT*CC];   // [t][c]
__device__ __align__(256) __nv_bfloat16 g_kh[BT*CC], g_kl[BT*CC];   // [t][c]
__device__ __align__(256) __half g_vh[BB*CC*TT], g_vl[BB*CC*TT];    // [b][c][t] fp16
__device__ __align__(256) float g_po[BB*QT_N*MAXSUB][BQ*CC];
__device__ __align__(256) float g_pl[BB*QT_N*MAXSUB][BQ];
__device__ int g_ctr;
__device__ int g_done[BB*QT_N];

// ---------------- helpers ---------------------------------------------------
__device__ __forceinline__ uint32_t smem_u32(const void* p) {
    uint32_t a;
    asm("{ .reg .u64 t; cvta.to.shared.u64 t, %1; cvt.u32.u64 %0, t; }"
        : "=r"(a) : "l"(p));
    return a;
}
__device__ __forceinline__ void ldm4(uint32_t* r, uint32_t a) {
    asm volatile("ldmatrix.sync.aligned.m8n8.x4.shared.b16 {%0,%1,%2,%3}, [%4];"
        : "=r"(r[0]), "=r"(r[1]), "=r"(r[2]), "=r"(r[3]) : "r"(a));
}
// mma: register-only, non-volatile -> scheduler may interleave freely
__device__ __forceinline__ void mma16816(float* c, const uint32_t* a,
                                         const uint32_t* b) {
    asm("mma.sync.aligned.m16n8k16.row.col.f32.bf16.bf16.f32 "
        "{%0,%1,%2,%3}, {%4,%5,%6,%7}, {%8,%9}, {%0,%1,%2,%3};"
        : "+f"(c[0]), "+f"(c[1]), "+f"(c[2]), "+f"(c[3])
        : "r"(a[0]), "r"(a[1]), "r"(a[2]), "r"(a[3]), "r"(b[0]), "r"(b[1]));
}
__device__ __forceinline__ void mma16816h(float* c, const uint32_t* a,
                                          const uint32_t* b) {
    asm("mma.sync.aligned.m16n8k16.row.col.f32.f16.f16.f32 "
        "{%0,%1,%2,%3}, {%4,%5,%6,%7}, {%8,%9}, {%0,%1,%2,%3};"
        : "+f"(c[0]), "+f"(c[1]), "+f"(c[2]), "+f"(c[3])
        : "r"(a[0]), "r"(a[1]), "r"(a[2]), "r"(a[3]), "r"(b[0]), "r"(b[1]));
}
#define CP_ASYNC16(dst, src) \
    asm volatile("cp.async.cg.shared.global [%0], [%1], 16;" \
                 :: "r"(dst), "l"(src))
#define CP_COMMIT() asm volatile("cp.async.commit_group;" ::: "memory")
#define CP_WAIT(n)  asm volatile("cp.async.wait_group %0;" :: "n"(n) : "memory")

// ---------------------------------------------------------------------------
// K1: tensorized QKV projection (unchanged from R11).
// ---------------------------------------------------------------------------
#define PX 136
#define SMX_H 0
#define SMX_L (SMX_H + 128*PX*2)
#define SMW_H (SMX_L + 128*PX*2)
#define SMW_L (SMW_H + 128*PX*2)
#define PROJ_SMEM (SMW_L + 128*PX*2)
#define PSTG 129

__global__ __launch_bounds__(256, 1) void qkv_proj_mma(
    const float* __restrict__ x,
    const float* __restrict__ Wq,
    const float* __restrict__ Wk,
    const float* __restrict__ Wv)
{
    extern __shared__ char smem[];
    const uint32_t sb = smem_u32(smem);
    const int widx = blockIdx.y;
    const float* __restrict__ W = (widx == 0) ? Wq : ((widx == 1) ? Wk : Wv);
    const int row0 = blockIdx.x * 128;
    const int tid = threadIdx.x, lane = tid & 31, wid = tid >> 5;
    const int wm = wid & 3, wn = wid >> 2;
    const int gr = lane >> 2, tc = lane & 3;

    if (blockIdx.x == 0 && widx == 0) {
        if (tid == 0) g_ctr = NCTA;
        if (tid < BB * QT_N) g_done[tid] = 0;
    }

#pragma unroll
    for (int f = tid; f < 128 * 32; f += 256) {
        const int r = f >> 5, c4 = (f & 31) * 4;
        float4 v = *(const float4*)&x[(size_t)(row0 + r) * CC + c4];
        __nv_bfloat162 h0 = __floats2bfloat162_rn(v.x, v.y);
        __nv_bfloat162 h1 = __floats2bfloat162_rn(v.z, v.w);
        __nv_bfloat162 l0 = __floats2bfloat162_rn(v.x - __low2float(h0),
                                                  v.y - __high2float(h0));
        __nv_bfloat162 l1 = __floats2bfloat162_rn(v.z - __low2float(h1),
                                                  v.w - __high2float(h1));
        const int o = (r * PX + c4) * 2;
        *(uint32_t*)(smem + SMX_H + o)     = *reinterpret_cast<uint32_t*>(&h0);
        *(uint32_t*)(smem + SMX_H + o + 4) = *reinterpret_cast<uint32_t*>(&h1);
        *(uint32_t*)(smem + SMX_L + o)     = *reinterpret_cast<uint32_t*>(&l0);
        *(uint32_t*)(smem + SMX_L + o + 4) = *reinterpret_cast<uint32_t*>(&l1);
    }
#pragma unroll
    for (int f = tid; f < 128 * 32; f += 256) {
        const int d = f >> 5, c4 = (f & 31) * 4;
        float4 v = *(const float4*)&W[(size_t)d * CC + c4];
        __nv_bfloat162 h0 = __floats2bfloat162_rn(v.x, v.y);
        __nv_bfloat162 h1 = __floats2bfloat162_rn(v.z, v.w);
        __nv_bfloat162 l0 = __floats2bfloat162_rn(v.x - __low2float(h0),
                                                  v.y - __high2float(h0));
        __nv_bfloat162 l1 = __floats2bfloat162_rn(v.z - __low2float(h1),
                                                  v.w - __high2float(h1));
        const int o = (d * PX + c4) * 2;
        *(uint32_t*)(smem + SMW_H + o)     = *reinterpret_cast<uint32_t*>(&h0);
        *(uint32_t*)(smem + SMW_H + o + 4) = *reinterpret_cast<uint32_t*>(&h1);
        *(uint32_t*)(smem + SMW_L + o)     = *reinterpret_cast<uint32_t*>(&l0);
        *(uint32_t*)(smem + SMW_L + o + 4) = *reinterpret_cast<uint32_t*>(&l1);
    }
    __syncthreads();

    const int lr = lane & 15, lh = lane >> 4;
    const int bn = (lane & 7) + ((lane >> 4) << 3);
    const int bk8 = ((lane >> 3) & 1) << 3;
    const uint32_t aXh = sb + SMX_H + (((wm * 32 + lr) * PX) + lh * 8) * 2;
    const uint32_t aXl = aXh + (SMX_L - SMX_H);
    const uint32_t aWh = sb + SMW_H + (((wn * 64 + bn) * PX) + bk8) * 2;
    const uint32_t aWl = aWh + (SMW_L - SMW_H);

    float acc[2][8][4];
#pragma unroll
    for (int mi = 0; mi < 2; mi++)
#pragma unroll
        for (int ni = 0; ni < 8; ni++)
#pragma unroll
            for (int e = 0; e < 4; e++) acc[mi][ni][e] = 0.0f;

#pragma unroll
    for (int ks = 0; ks < 8; ++ks) {
        uint32_t ah[2][4], al[2][4], bh[8][2], bl[8][2];
        ldm4(ah[0], aXh + ks * 32);
        ldm4(ah[1], aXh + 16 * PX * 2 + ks * 32);
        ldm4(al[0], aXl + ks * 32);
        ldm4(al[1], aXl + 16 * PX * 2 + ks * 32);
#pragma unroll
        for (int p = 0; p < 4; p++) {
            ldm4(&bh[2 * p][0], aWh + p * 16 * PX * 2 + ks * 32);
            ldm4(&bl[2 * p][0], aWl + p * 16 * PX * 2 + ks * 32);
        }
#pragma unroll
        for (int mi = 0; mi < 2; mi++)
#pragma unroll
            for (int ni = 0; ni < 8; ni++) {
                mma16816(acc[mi][ni], ah[mi], bh[ni]);
                mma16816(acc[mi][ni], ah[mi], bl[ni]);
                mma16816(acc[mi][ni], al[mi], bh[ni]);
            }
    }

    if (widx < 2) {
        __nv_bfloat16* oh = (widx == 0) ? g_qh : g_kh;
        __nv_bfloat16* ol = (widx == 0) ? g_ql : g_kl;
        const float sc = (widx == 0) ? SCALE_L2E : 1.0f;
#pragma unroll
        for (int mi = 0; mi < 2; mi++)
#pragma unroll
            for (int half = 0; half < 2; half++) {
                const int row = wm * 32 + mi * 16 + gr + half * 8;
                const size_t rb = (size_t)(row0 + row) * CC;
#pragma unroll
                for (int ni = 0; ni < 8; ni++) {
                    const int col = wn * 64 + ni * 8 + tc * 2;
                    float y0 = acc[mi][ni][half * 2 + 0] * sc;
                    float y1 = acc[mi][ni][half * 2 + 1] * sc;
                    __nv_bfloat162 H = __floats2bfloat162_rn(y0, y1);
                    __nv_bfloat162 L = __floats2bfloat162_rn(y0 - __low2float(H),
                                                             y1 - __high2float(H));
                    *(uint32_t*)&oh[rb + col] = *reinterpret_cast<uint32_t*>(&H);
                    *(uint32_t*)&ol[rb + col] = *reinterpret_cast<uint32_t*>(&L);
                }
            }
    } else {
        // ---- V: stage fp32, transposed fp16 hi/lo store ----
        __syncthreads();
        float* stg = (float*)smem;
#pragma unroll
        for (int mi = 0; mi < 2; mi++)
#pragma unroll
            for (int half = 0; half < 2; half++) {
                const int row = wm * 32 + mi * 16 + gr + half * 8;
#pragma unroll
                for (int ni = 0; ni < 8; ni++) {
                    const int col = wn * 64 + ni * 8 + tc * 2;
                    stg[row * PSTG + col]     = acc[mi][ni][half * 2 + 0];
                    stg[row * PSTG + col + 1] = acc[mi][ni][half * 2 + 1];
                }
            }
        __syncthreads();
        const int b = row0 >> 12, t0 = row0 & (TT - 1);
        __half* vh = g_vh + (size_t)b * CC * TT + t0;
        __half* vl = g_vl + (size_t)b * CC * TT + t0;
#pragma unroll 1
        for (int c = wid; c < 128; c += 8) {
            float v[4];
#pragma unroll
            for (int i = 0; i < 4; i++)
                v[i] = stg[(lane * 4 + i) * PSTG + c];
            __half2 h0 = __floats2half2_rn(v[0], v[1]);
            __half2 h1 = __floats2half2_rn(v[2], v[3]);
            __half2 l0 = __floats2half2_rn(v[0] - __low2float(h0),
                                           v[1] - __high2float(h0));
            __half2 l1 = __floats2half2_rn(v[2] - __low2float(h1),
                                           v[3] - __high2float(h1));
            uint2 Hp = make_uint2(*reinterpret_cast<uint32_t*>(&h0),
                                  *reinterpret_cast<uint32_t*>(&h1));
            uint2 Lp = make_uint2(*reinterpret_cast<uint32_t*>(&l0),
                                  *reinterpret_cast<uint32_t*>(&l1));
            *(uint2*)&vh[(size_t)c * TT + lane * 4] = Hp;
            *(uint2*)&vl[(size_t)c * TT + lane * 4] = Lp;
        }
    }
}

// ---------------------------------------------------------------------------
// K2: persistent flash attention + fused combine. Software-pipelined frags.
// ---------------------------------------------------------------------------
#define PQ 136
#define PK 136
#define PV 72
#define SM_QH 0
#define SM_QL (128*PQ*2)                 // 34816
#define SM_KV (2*128*PQ*2)               // 69632
#define KBUF  (64*PK*2)                  // 17408
#define OFF_KH 0
#define OFF_KL KBUF
#define OFF_VH (2*KBUF)
#define OFF_VL (2*KBUF + 128*PV*2)
#define BUFSZ  (2*KBUF + 2*128*PV*2)     // 71680
#define SM_NEXT (SM_KV + 2*BUFSZ)        // +0 next, +4 flag
#define SM_INVL (SM_NEXT + 16)
#define FLASH_SMEM (SM_INVL + 128*4)

__device__ __forceinline__ void prefetch_kv(uint32_t buf, int b, int j, int tid)
{
    const __nv_bfloat16* kh = g_kh + (size_t)(b * TT + j * BKT) * CC;
    const __nv_bfloat16* kl = g_kl + (size_t)(b * TT + j * BKT) * CC;
#pragma unroll
    for (int u = 0; u < 4; u++) {
        const int f = tid + u * 256, r = f >> 4, c8 = (f & 15) << 3;
        const uint32_t o = buf + OFF_KH + (r * PK + c8) * 2;
        CP_ASYNC16(o, kh + r * CC + c8);
        CP_ASYNC16(o + (OFF_KL - OFF_KH), kl + r * CC + c8);
    }
    const __half* vh = g_vh + (size_t)b * CC * TT + j * BKT;
    const __half* vl = g_vl + (size_t)b * CC * TT + j * BKT;
#pragma unroll
    for (int u = 0; u < 4; u++) {
        const int f = tid + u * 256, d = f >> 3, c8 = (f & 7) << 3;
        const uint32_t o = buf + OFF_VH + (d * PV + c8) * 2;
        CP_ASYNC16(o, vh + (size_t)d * TT + c8);
        CP_ASYNC16(o + (OFF_VL - OFF_VH), vl + (size_t)d * TT + c8);
    }
}

__global__ __launch_bounds__(256, 1) void flash_attn(float* __restrict__ out)
{
    extern __shared__ char smem[];
    const uint32_t sb = smem_u32(smem);
    const int tid = threadIdx.x, lane = tid & 31, wid = tid >> 5;
    const int gr = lane >> 2, tc = lane & 3;

    const int lr = lane & 15, lh = lane >> 4;
    const int bn = (lane & 7) + ((lane >> 4) << 3);
    const int bk8 = ((lane >> 3) & 1) << 3;

    const uint32_t aQh = sb + SM_QH + (((wid * 16 + lr) * PQ) + lh * 8) * 2;
    const uint32_t aQl = aQh + (SM_QL - SM_QH);
    const uint32_t aKrel = (bn * PK + bk8) * 2;
    const uint32_t aVrel = (bn * PV + bk8) * 2;

    const int row_a = wid * 16 + gr;
    const int row_b = row_a + 8;
    int* s_next = (int*)(smem + SM_NEXT);
    int* s_flag = (int*)(smem + SM_NEXT + 4);

    int slice = blockIdx.x;
    while (slice < NSLICES) {
        // ---- decode slice -> (b, qt, sub, kv0, kv1, ns) ----
        int rem = slice, qt = 31, ns = 1;
#pragma unroll 1
        for (qt = 31; qt > 0; --qt) {
            ns = (2 * qt + 2 + CH - 1) / CH;
            if (rem < 4 * ns) break;
            rem -= 4 * ns;
        }
        if (qt == 0) ns = 1;
        const int b = rem & 3, sub = rem >> 2;
        const int it = 2 * qt + 2;
        const int base = it / ns, r2 = it - base * ns;
        const int kv0 = sub * base + (sub < r2 ? sub : r2);
        const int kv1 = kv0 + base + (sub < r2 ? 1 : 0);
        const int slot = (b * QT_N + qt) * MAXSUB + sub;

        // ---- prologue: cp.async Q (group 1) then KV0 (group 2) ----
        {
            const __nv_bfloat16* qh = g_qh + (size_t)(b * TT + qt * BQ) * CC;
            const __nv_bfloat16* ql = g_ql + (size_t)(b * TT + qt * BQ) * CC;
#pragma unroll
            for (int u = 0; u < 8; u++) {
                const int f = tid + u * 256, r = f >> 4, c8 = (f & 15) << 3;
                const uint32_t o = sb + SM_QH + (r * PQ + c8) * 2;
                CP_ASYNC16(o, qh + r * CC + c8);
                CP_ASYNC16(o + (SM_QL - SM_QH), ql + r * CC + c8);
            }
        }
        CP_COMMIT();
        prefetch_kv(sb + SM_KV, b, kv0, tid);
        CP_COMMIT();
        CP_WAIT(1);                      // Q complete; KV0 may be in flight
        __syncthreads();                 // Q visible to all warps

        float o[16][4];
#pragma unroll
        for (int ni = 0; ni < 16; ni++)
#pragma unroll
            for (int e = 0; e < 4; e++) o[ni][e] = 0.0f;
        float lsumA = 0.0f, lsumB = 0.0f;

        int cur = 0;
#pragma unroll 1
        for (int j = kv0; j < kv1; ++j, cur ^= 1) {
            __syncthreads();             // prev-buffer reads complete
            if (j + 1 < kv1) {
                prefetch_kv(sb + SM_KV + (cur ^ 1) * BUFSZ, b, j + 1, tid);
                CP_COMMIT();
                CP_WAIT(1);              // tile j complete, j+1 in flight
            } else {
                CP_WAIT(0);
            }
            __syncthreads();             // tile j visible

            const uint32_t kb = sb + SM_KV + cur * BUFSZ;
            const uint32_t aKh = kb + OFF_KH + aKrel;
            const uint32_t aKl = kb + OFF_KL + aKrel;
            const uint32_t aVh = kb + OFF_VH + aVrel;
            const uint32_t aVl = kb + OFF_VL + aVrel;

            // ---- S = Q K^T (16x64), bf16 3-term, pipelined fragments ----
            float s[8][4];
#pragma unroll
            for (int ni = 0; ni < 8; ni++)
#pragma unroll
                for (int e = 0; e < 4; e++) s[ni][e] = 0.0f;

            uint32_t qh2[2][4], ql2[2][4], bh2[2][4], bl2[2][4];
            ldm4(qh2[0], aQh);
            ldm4(ql2[0], aQl);
            ldm4(bh2[0], aKh);
            ldm4(bl2[0], aKl);
#pragma unroll
            for (int t = 0; t < 32; ++t) {
                const int ks = t >> 2, p = t & 3;
                const int cb = t & 1, nb = cb ^ 1;
                if (t < 31) {                  // prefetch next (ks,p) B frags
                    const int tn = t + 1, ksn = tn >> 2, pn = tn & 3;
                    ldm4(bh2[nb], aKh + pn * 16 * PK * 2 + ksn * 32);
                    ldm4(bl2[nb], aKl + pn * 16 * PK * 2 + ksn * 32);
                    if (pn == 0) {             // new ks -> prefetch Q frags
                        ldm4(qh2[ksn & 1], aQh + ksn * 32);
                        ldm4(ql2[ksn & 1], aQl + ksn * 32);
                    }
                }
                const uint32_t* qa = qh2[ks & 1];
                const uint32_t* ql4 = ql2[ks & 1];
                mma16816(s[2 * p],     qa,  &bh2[cb][0]);
                mma16816(s[2 * p + 1], qa,  &bh2[cb][2]);
                mma16816(s[2 * p],     qa,  &bl2[cb][0]);
                mma16816(s[2 * p + 1], qa,  &bl2[cb][2]);
                mma16816(s[2 * p],     ql4, &bh2[cb][0]);
                mma16816(s[2 * p + 1], ql4, &bh2[cb][2]);
            }

            // ---- softmax -> fp16 Ph A-fragments; l over rounded Ph ----
            const int srel = j * BKT - qt * BQ;
            uint32_t ph[4][4];
#pragma unroll
            for (int ni = 0; ni < 8; ni++) {
                const int ksv = ni >> 1, hh = (ni & 1) * 2;
                const int col = srel + ni * 8 + tc * 2;
                float p0 = (col     <= row_a) ? exp2f(s[ni][0]) : 0.0f;
                float p1 = (col + 1 <= row_a) ? exp2f(s[ni][1]) : 0.0f;
                float p2 = (col     <= row_b) ? exp2f(s[ni][2]) : 0.0f;
                float p3 = (col + 1 <= row_b) ? exp2f(s[ni][3]) : 0.0f;
                __half2 H0 = __floats2half2_rn(p0, p1);
                __half2 H1 = __floats2half2_rn(p2, p3);
                lsumA += __low2float(H0) + __high2float(H0);
                lsumB += __low2float(H1) + __high2float(H1);
                ph[ksv][hh]     = *reinterpret_cast<uint32_t*>(&H0);
                ph[ksv][hh + 1] = *reinterpret_cast<uint32_t*>(&H1);
            }

            // ---- O += P V (16x128), fp16 2-term, pipelined fragments ----
            uint32_t vh2[2][4], vl2[2][4];
            ldm4(vh2[0], aVh);
            ldm4(vl2[0], aVl);
#pragma unroll
            for (int t = 0; t < 32; ++t) {
                const int ksv = t >> 3, p = t & 7;
                const int cb = t & 1, nb = cb ^ 1;
                if (t < 31) {
                    const int tn = t + 1, ksn = tn >> 3, pn = tn & 7;
                    ldm4(vh2[nb], aVh + pn * 16 * PV * 2 + ksn * 32);
                    ldm4(vl2[nb], aVl + pn * 16 * PV * 2 + ksn * 32);
                }
                mma16816h(o[2 * p],     ph[ksv], &vh2[cb][0]);
                mma16816h(o[2 * p + 1], ph[ksv], &vh2[cb][2]);
                mma16816h(o[2 * p],     ph[ksv], &vl2[cb][0]);
                mma16816h(o[2 * p + 1], ph[ksv], &vl2[cb][2]);
            }
        }

        // ---- slice epilogue: l reduce + partial writes ----
        lsumA += __shfl_xor_sync(0xffffffffu, lsumA, 1);
        lsumA += __shfl_xor_sync(0xffffffffu, lsumA, 2);
        lsumB += __shfl_xor_sync(0xffffffffu, lsumB, 1);
        lsumB += __shfl_xor_sync(0xffffffffu, lsumB, 2);
        if (tc == 0) {
            g_pl[slot][row_a] = lsumA;
            g_pl[slot][row_b] = lsumB;
        }
        float* po = g_po[slot];
#pragma unroll
        for (int ni = 0; ni < 16; ni++) {
            const int col = ni * 8 + tc * 2;
            *(float2*)&po[row_a * CC + col] = make_float2(o[ni][0], o[ni][1]);
            *(float2*)&po[row_b * CC + col] = make_float2(o[ni][2], o[ni][3]);
        }

        // ---- fused combine: last-arriving CTA for this (b,qt) finishes it ----
        __threadfence();
        __syncthreads();
        if (tid == 0) {
            int old = atomicAdd(&g_done[b * QT_N + qt], 1);
            *s_flag = (old == ns - 1) ? 1 : 0;
        }
        __syncthreads();
        if (*s_flag) {
            __threadfence();
            const int s0 = (b * QT_N + qt) * MAXSUB;
            float* invl = (float*)(smem + SM_INVL);
            for (int r = tid; r < 128; r += 256) {
                float ssum = 0.0f;
                for (int u = 0; u < ns; u++) ssum += g_pl[s0 + u][r];
                invl[r] = 1.0f / ssum;
            }
            __syncthreads();
            float* dst = out + (size_t)(b * TT + qt * BQ) * CC;
#pragma unroll 2
            for (int f = tid; f < BQ * CC / 4; f += 256) {
                const int row = f >> 5;
                float4 a = *(const float4*)&g_po[s0][f * 4];
                for (int u = 1; u < ns; u++) {
                    float4 v = *(const float4*)&g_po[s0 + u][f * 4];
                    a.x += v.x; a.y += v.y; a.z += v.z; a.w += v.w;
                }
                const float inv = invl[row];
                a.x *= inv; a.y *= inv; a.z *= inv; a.w *= inv;
                *(float4*)&dst[f * 4] = a;
            }
        }

        // ---- pop next slice ----
        if (tid == 0) *s_next = atomicAdd(&g_ctr, 1);
        __syncthreads();
        slice = *s_next;
    }
}

// ---------------------------------------------------------------------------
extern "C" void kernel_launch(void* const* d_in, const int* in_sizes, int n_in,
                              void* d_out, int out_size)
{
    const float* x  = (const float*)d_in[0];
    const float* Wq = (const float*)d_in[1];
    const float* Wk = (const float*)d_in[2];
    const float* Wv = (const float*)d_in[3];
    float* out = (float*)d_out;

    cudaFuncSetAttribute(flash_attn,
                         cudaFuncAttributeMaxDynamicSharedMemorySize,
                         FLASH_SMEM);
    cudaFuncSetAttribute(qkv_proj_mma,
                         cudaFuncAttributeMaxDynamicSharedMemorySize,
                         PROJ_SMEM);

    qkv_proj_mma<<<dim3(BT / 128, 3), 256, PROJ_SMEM>>>(x, Wq, Wk, Wv);
    flash_attn<<<NCTA, 256, FLASH_SMEM>>>(out);
}

// round 13
// speedup vs baseline: 1.1565x; 1.1565x over previous
#include <cuda_runtime.h>
#include <cuda_bf16.h>
#include <cuda_fp16.h>
#include <cstdint>

// CausalSelfAttention: B=4, T=4096, C=128, fp32 in/out.
// K1: tensorized QKV projection (mma.sync bf16 hi/lo x3-term for Q/K;
//     V emitted as SINGLE fp16). Resets work queue.
// K2: persistent flash attention: warp-private 16-row tiles; S = bf16 3-term;
//     PV = fp16 1xV (P hi only, l summed over rounded Ph); cp.async staged Q
//     + double-buffered K/V; split-KV queue (CH=6); fused per-tile combine.

#define BB 4
#define TT 4096
#define CC 128
#define BT (BB*TT)
#define QT_N 32
#define SCALE_L2E (0.08838834764831845f * 1.4426950408889634f)

#define BQ 128
#define BKT 64
#define CH 6
#define MAXSUB 11
#define NSLICES 748     // 4 * sum_qt ceil((2qt+2)/6)
#define NCTA 148

// ---------------- scratch (device globals; no cudaMalloc) -------------------
__device__ __align__(256) __nv_bfloat16 g_qh[BT*CC], g_ql[BT*CC];   // [t][c]
__device__ __align__(256) __nv_bfloat16 g_kh[BT*CC], g_kl[BT*CC];   // [t][c]
__device__ __align__(256) __half g_v[BB*CC*TT];                     // [b][c][t] fp16
__device__ __align__(256) float g_po[BB*QT_N*MAXSUB][BQ*CC];
__device__ __align__(256) float g_pl[BB*QT_N*MAXSUB][BQ];
__device__ int g_ctr;
__device__ int g_done[BB*QT_N];

// ---------------- helpers ---------------------------------------------------
__device__ __forceinline__ uint32_t smem_u32(const void* p) {
    uint32_t a;
    asm("{ .reg .u64 t; cvta.to.shared.u64 t, %1; cvt.u32.u64 %0, t; }"
        : "=r"(a) : "l"(p));
    return a;
}
__device__ __forceinline__ void ldm4(uint32_t* r, uint32_t a) {
    asm volatile("ldmatrix.sync.aligned.m8n8.x4.shared.b16 {%0,%1,%2,%3}, [%4];"
        : "=r"(r[0]), "=r"(r[1]), "=r"(r[2]), "=r"(r[3]) : "r"(a));
}
__device__ __forceinline__ void mma16816(float* c, const uint32_t* a,
                                         const uint32_t* b) {
    asm("mma.sync.aligned.m16n8k16.row.col.f32.bf16.bf16.f32 "
        "{%0,%1,%2,%3}, {%4,%5,%6,%7}, {%8,%9}, {%0,%1,%2,%3};"
        : "+f"(c[0]), "+f"(c[1]), "+f"(c[2]), "+f"(c[3])
        : "r"(a[0]), "r"(a[1]), "r"(a[2]), "r"(a[3]), "r"(b[0]), "r"(b[1]));
}
__device__ __forceinline__ void mma16816h(float* c, const uint32_t* a,
                                          const uint32_t* b) {
    asm("mma.sync.aligned.m16n8k16.row.col.f32.f16.f16.f32 "
        "{%0,%1,%2,%3}, {%4,%5,%6,%7}, {%8,%9}, {%0,%1,%2,%3};"
        : "+f"(c[0]), "+f"(c[1]), "+f"(c[2]), "+f"(c[3])
        : "r"(a[0]), "r"(a[1]), "r"(a[2]), "r"(a[3]), "r"(b[0]), "r"(b[1]));
}
#define CP_ASYNC16(dst, src) \
    asm volatile("cp.async.cg.shared.global [%0], [%1], 16;" \
                 :: "r"(dst), "l"(src))
#define CP_COMMIT() asm volatile("cp.async.commit_group;" ::: "memory")
#define CP_WAIT(n)  asm volatile("cp.async.wait_group %0;" :: "n"(n) : "memory")

// ---------------------------------------------------------------------------
// K1: tensorized QKV projection (V epilogue now single fp16).
// ---------------------------------------------------------------------------
#define PX 136
#define SMX_H 0
#define SMX_L (SMX_H + 128*PX*2)
#define SMW_H (SMX_L + 128*PX*2)
#define SMW_L (SMW_H + 128*PX*2)
#define PROJ_SMEM (SMW_L + 128*PX*2)
#define PSTG 129

__global__ __launch_bounds__(256, 1) void qkv_proj_mma(
    const float* __restrict__ x,
    const float* __restrict__ Wq,
    const float* __restrict__ Wk,
    const float* __restrict__ Wv)
{
    extern __shared__ char smem[];
    const uint32_t sb = smem_u32(smem);
    const int widx = blockIdx.y;
    const float* __restrict__ W = (widx == 0) ? Wq : ((widx == 1) ? Wk : Wv);
    const int row0 = blockIdx.x * 128;
    const int tid = threadIdx.x, lane = tid & 31, wid = tid >> 5;
    const int wm = wid & 3, wn = wid >> 2;
    const int gr = lane >> 2, tc = lane & 3;

    if (blockIdx.x == 0 && widx == 0) {
        if (tid == 0) g_ctr = NCTA;
        if (tid < BB * QT_N) g_done[tid] = 0;
    }

#pragma unroll
    for (int f = tid; f < 128 * 32; f += 256) {
        const int r = f >> 5, c4 = (f & 31) * 4;
        float4 v = *(const float4*)&x[(size_t)(row0 + r) * CC + c4];
        __nv_bfloat162 h0 = __floats2bfloat162_rn(v.x, v.y);
        __nv_bfloat162 h1 = __floats2bfloat162_rn(v.z, v.w);
        __nv_bfloat162 l0 = __floats2bfloat162_rn(v.x - __low2float(h0),
                                                  v.y - __high2float(h0));
        __nv_bfloat162 l1 = __floats2bfloat162_rn(v.z - __low2float(h1),
                                                  v.w - __high2float(h1));
        const int o = (r * PX + c4) * 2;
        *(uint32_t*)(smem + SMX_H + o)     = *reinterpret_cast<uint32_t*>(&h0);
        *(uint32_t*)(smem + SMX_H + o + 4) = *reinterpret_cast<uint32_t*>(&h1);
        *(uint32_t*)(smem + SMX_L + o)     = *reinterpret_cast<uint32_t*>(&l0);
        *(uint32_t*)(smem + SMX_L + o + 4) = *reinterpret_cast<uint32_t*>(&l1);
    }
#pragma unroll
    for (int f = tid; f < 128 * 32; f += 256) {
        const int d = f >> 5, c4 = (f & 31) * 4;
        float4 v = *(const float4*)&W[(size_t)d * CC + c4];
        __nv_bfloat162 h0 = __floats2bfloat162_rn(v.x, v.y);
        __nv_bfloat162 h1 = __floats2bfloat162_rn(v.z, v.w);
        __nv_bfloat162 l0 = __floats2bfloat162_rn(v.x - __low2float(h0),
                                                  v.y - __high2float(h0));
        __nv_bfloat162 l1 = __floats2bfloat162_rn(v.z - __low2float(h1),
                                                  v.w - __high2float(h1));
        const int o = (d * PX + c4) * 2;
        *(uint32_t*)(smem + SMW_H + o)     = *reinterpret_cast<uint32_t*>(&h0);
        *(uint32_t*)(smem + SMW_H + o + 4) = *reinterpret_cast<uint32_t*>(&h1);
        *(uint32_t*)(smem + SMW_L + o)     = *reinterpret_cast<uint32_t*>(&l0);
        *(uint32_t*)(smem + SMW_L + o + 4) = *reinterpret_cast<uint32_t*>(&l1);
    }
    __syncthreads();

    const int lr = lane & 15, lh = lane >> 4;
    const int bn = (lane & 7) + ((lane >> 4) << 3);
    const int bk8 = ((lane >> 3) & 1) << 3;
    const uint32_t aXh = sb + SMX_H + (((wm * 32 + lr) * PX) + lh * 8) * 2;
    const uint32_t aXl = aXh + (SMX_L - SMX_H);
    const uint32_t aWh = sb + SMW_H + (((wn * 64 + bn) * PX) + bk8) * 2;
    const uint32_t aWl = aWh + (SMW_L - SMW_H);

    float acc[2][8][4];
#pragma unroll
    for (int mi = 0; mi < 2; mi++)
#pragma unroll
        for (int ni = 0; ni < 8; ni++)
#pragma unroll
            for (int e = 0; e < 4; e++) acc[mi][ni][e] = 0.0f;

#pragma unroll
    for (int ks = 0; ks < 8; ++ks) {
        uint32_t ah[2][4], al[2][4], bh[8][2], bl[8][2];
        ldm4(ah[0], aXh + ks * 32);
        ldm4(ah[1], aXh + 16 * PX * 2 + ks * 32);
        ldm4(al[0], aXl + ks * 32);
        ldm4(al[1], aXl + 16 * PX * 2 + ks * 32);
#pragma unroll
        for (int p = 0; p < 4; p++) {
            ldm4(&bh[2 * p][0], aWh + p * 16 * PX * 2 + ks * 32);
            ldm4(&bl[2 * p][0], aWl + p * 16 * PX * 2 + ks * 32);
        }
#pragma unroll
        for (int mi = 0; mi < 2; mi++)
#pragma unroll
            for (int ni = 0; ni < 8; ni++) {
                mma16816(acc[mi][ni], ah[mi], bh[ni]);
                mma16816(acc[mi][ni], ah[mi], bl[ni]);
                mma16816(acc[mi][ni], al[mi], bh[ni]);
            }
    }

    if (widx < 2) {
        __nv_bfloat16* oh = (widx == 0) ? g_qh : g_kh;
        __nv_bfloat16* ol = (widx == 0) ? g_ql : g_kl;
        const float sc = (widx == 0) ? SCALE_L2E : 1.0f;
#pragma unroll
        for (int mi = 0; mi < 2; mi++)
#pragma unroll
            for (int half = 0; half < 2; half++) {
                const int row = wm * 32 + mi * 16 + gr + half * 8;
                const size_t rb = (size_t)(row0 + row) * CC;
#pragma unroll
                for (int ni = 0; ni < 8; ni++) {
                    const int col = wn * 64 + ni * 8 + tc * 2;
                    float y0 = acc[mi][ni][half * 2 + 0] * sc;
                    float y1 = acc[mi][ni][half * 2 + 1] * sc;
                    __nv_bfloat162 H = __floats2bfloat162_rn(y0, y1);
                    __nv_bfloat162 L = __floats2bfloat162_rn(y0 - __low2float(H),
                                                             y1 - __high2float(H));
                    *(uint32_t*)&oh[rb + col] = *reinterpret_cast<uint32_t*>(&H);
                    *(uint32_t*)&ol[rb + col] = *reinterpret_cast<uint32_t*>(&L);
                }
            }
    } else {
        // ---- V: stage fp32, transposed single-fp16 store ----
        __syncthreads();
        float* stg = (float*)smem;
#pragma unroll
        for (int mi = 0; mi < 2; mi++)
#pragma unroll
            for (int half = 0; half < 2; half++) {
                const int row = wm * 32 + mi * 16 + gr + half * 8;
#pragma unroll
                for (int ni = 0; ni < 8; ni++) {
                    const int col = wn * 64 + ni * 8 + tc * 2;
                    stg[row * PSTG + col]     = acc[mi][ni][half * 2 + 0];
                    stg[row * PSTG + col + 1] = acc[mi][ni][half * 2 + 1];
                }
            }
        __syncthreads();
        const int b = row0 >> 12, t0 = row0 & (TT - 1);
        __half* vv = g_v + (size_t)b * CC * TT + t0;
#pragma unroll 1
        for (int c = wid; c < 128; c += 8) {
            float v[4];
#pragma unroll
            for (int i = 0; i < 4; i++)
                v[i] = stg[(lane * 4 + i) * PSTG + c];
            __half2 h0 = __floats2half2_rn(v[0], v[1]);
            __half2 h1 = __floats2half2_rn(v[2], v[3]);
            uint2 Hp = make_uint2(*reinterpret_cast<uint32_t*>(&h0),
                                  *reinterpret_cast<uint32_t*>(&h1));
            *(uint2*)&vv[(size_t)c * TT + lane * 4] = Hp;
        }
    }
}

// ---------------------------------------------------------------------------
// K2: persistent flash attention + fused combine. V single fp16.
// ---------------------------------------------------------------------------
#define PQ 136
#define PK 136
#define PV 72
#define SM_QH 0
#define SM_QL (128*PQ*2)                 // 34816
#define SM_KV (2*128*PQ*2)               // 69632
#define KBUF  (64*PK*2)                  // 17408
#define OFF_KH 0
#define OFF_KL KBUF
#define OFF_V  (2*KBUF)                  // 34816
#define BUFSZ  (2*KBUF + 128*PV*2)       // 53248
#define SM_NEXT (SM_KV + 2*BUFSZ)        // +0 next, +4 flag
#define SM_INVL (SM_NEXT + 16)
#define FLASH_SMEM (SM_INVL + 128*4)

__device__ __forceinline__ void prefetch_kv(uint32_t buf, int b, int j, int tid)
{
    const __nv_bfloat16* kh = g_kh + (size_t)(b * TT + j * BKT) * CC;
    const __nv_bfloat16* kl = g_kl + (size_t)(b * TT + j * BKT) * CC;
#pragma unroll
    for (int u = 0; u < 4; u++) {
        const int f = tid + u * 256, r = f >> 4, c8 = (f & 15) << 3;
        const uint32_t o = buf + OFF_KH + (r * PK + c8) * 2;
        CP_ASYNC16(o, kh + r * CC + c8);
        CP_ASYNC16(o + (OFF_KL - OFF_KH), kl + r * CC + c8);
    }
    const __half* vv = g_v + (size_t)b * CC * TT + j * BKT;
#pragma unroll
    for (int u = 0; u < 4; u++) {
        const int f = tid + u * 256, d = f >> 3, c8 = (f & 7) << 3;
        CP_ASYNC16(buf + OFF_V + (d * PV + c8) * 2, vv + (size_t)d * TT + c8);
    }
}

__global__ __launch_bounds__(256, 1) void flash_attn(float* __restrict__ out)
{
    extern __shared__ char smem[];
    const uint32_t sb = smem_u32(smem);
    const int tid = threadIdx.x, lane = tid & 31, wid = tid >> 5;
    const int gr = lane >> 2, tc = lane & 3;

    const int lr = lane & 15, lh = lane >> 4;
    const int bn = (lane & 7) + ((lane >> 4) << 3);
    const int bk8 = ((lane >> 3) & 1) << 3;

    const uint32_t aQh = sb + SM_QH + (((wid * 16 + lr) * PQ) + lh * 8) * 2;
    const uint32_t aQl = aQh + (SM_QL - SM_QH);
    const uint32_t aKrel = (bn * PK + bk8) * 2;
    const uint32_t aVrel = (bn * PV + bk8) * 2;

    const int row_a = wid * 16 + gr;
    const int row_b = row_a + 8;
    int* s_next = (int*)(smem + SM_NEXT);
    int* s_flag = (int*)(smem + SM_NEXT + 4);

    int slice = blockIdx.x;
    while (slice < NSLICES) {
        // ---- decode slice -> (b, qt, sub, kv0, kv1, ns) ----
        int rem = slice, qt = 31, ns = 1;
#pragma unroll 1
        for (qt = 31; qt > 0; --qt) {
            ns = (2 * qt + 2 + CH - 1) / CH;
            if (rem < 4 * ns) break;
            rem -= 4 * ns;
        }
        if (qt == 0) ns = 1;
        const int b = rem & 3, sub = rem >> 2;
        const int it = 2 * qt + 2;
        const int base = it / ns, r2 = it - base * ns;
        const int kv0 = sub * base + (sub < r2 ? sub : r2);
        const int kv1 = kv0 + base + (sub < r2 ? 1 : 0);
        const int slot = (b * QT_N + qt) * MAXSUB + sub;

        // ---- prologue: cp.async Q (group 1) then KV0 (group 2) ----
        {
            const __nv_bfloat16* qh = g_qh + (size_t)(b * TT + qt * BQ) * CC;
            const __nv_bfloat16* ql = g_ql + (size_t)(b * TT + qt * BQ) * CC;
#pragma unroll
            for (int u = 0; u < 8; u++) {
                const int f = tid + u * 256, r = f >> 4, c8 = (f & 15) << 3;
                const uint32_t o = sb + SM_QH + (r * PQ + c8) * 2;
                CP_ASYNC16(o, qh + r * CC + c8);
                CP_ASYNC16(o + (SM_QL - SM_QH), ql + r * CC + c8);
            }
        }
        CP_COMMIT();
        prefetch_kv(sb + SM_KV, b, kv0, tid);
        CP_COMMIT();
        CP_WAIT(1);                      // Q complete; KV0 may be in flight
        __syncthreads();                 // Q visible to all warps
        uint32_t qah[8][4];
#pragma unroll
        for (int ks = 0; ks < 8; ++ks)
            ldm4(qah[ks], aQh + ks * 32);

        float o[16][4];
#pragma unroll
        for (int ni = 0; ni < 16; ni++)
#pragma unroll
            for (int e = 0; e < 4; e++) o[ni][e] = 0.0f;
        float lsumA = 0.0f, lsumB = 0.0f;

        int cur = 0;
#pragma unroll 1
        for (int j = kv0; j < kv1; ++j, cur ^= 1) {
            __syncthreads();             // prev-buffer reads complete
            if (j + 1 < kv1) {
                prefetch_kv(sb + SM_KV + (cur ^ 1) * BUFSZ, b, j + 1, tid);
                CP_COMMIT();
                CP_WAIT(1);              // tile j complete, j+1 in flight
            } else {
                CP_WAIT(0);
            }
            __syncthreads();             // tile j visible

            const uint32_t kb = sb + SM_KV + cur * BUFSZ;
            const uint32_t aKh = kb + OFF_KH + aKrel;
            const uint32_t aKl = kb + OFF_KL + aKrel;
            const uint32_t aV  = kb + OFF_V  + aVrel;

            // ---- S = Q K^T (16x64), bf16 3-term: Qh*Kh + Qh*Kl + Ql*Kh ----
            float s[8][4];
#pragma unroll
            for (int ni = 0; ni < 8; ni++)
#pragma unroll
                for (int e = 0; e < 4; e++) s[ni][e] = 0.0f;

#pragma unroll
            for (int ks = 0; ks < 8; ++ks) {
                uint32_t qal4[4];
                ldm4(qal4, aQl + ks * 32);
#pragma unroll
                for (int p = 0; p < 4; p++) {
                    uint32_t bh4[4], bl4[4];
                    ldm4(bh4, aKh + p * 16 * PK * 2 + ks * 32);
                    ldm4(bl4, aKl + p * 16 * PK * 2 + ks * 32);
                    mma16816(s[2 * p],     qah[ks], &bh4[0]);
                    mma16816(s[2 * p + 1], qah[ks], &bh4[2]);
                    mma16816(s[2 * p],     qah[ks], &bl4[0]);
                    mma16816(s[2 * p + 1], qah[ks], &bl4[2]);
                    mma16816(s[2 * p],     qal4,    &bh4[0]);
                    mma16816(s[2 * p + 1], qal4,    &bh4[2]);
                }
            }

            // ---- softmax -> fp16 Ph A-fragments; l over rounded Ph ----
            const int srel = j * BKT - qt * BQ;
            uint32_t ph[4][4];
#pragma unroll
            for (int ni = 0; ni < 8; ni++) {
                const int ksv = ni >> 1, hh = (ni & 1) * 2;
                const int col = srel + ni * 8 + tc * 2;
                float p0 = (col     <= row_a) ? exp2f(s[ni][0]) : 0.0f;
                float p1 = (col + 1 <= row_a) ? exp2f(s[ni][1]) : 0.0f;
                float p2 = (col     <= row_b) ? exp2f(s[ni][2]) : 0.0f;
                float p3 = (col + 1 <= row_b) ? exp2f(s[ni][3]) : 0.0f;
                __half2 H0 = __floats2half2_rn(p0, p1);
                __half2 H1 = __floats2half2_rn(p2, p3);
                lsumA += __low2float(H0) + __high2float(H0);
                lsumB += __low2float(H1) + __high2float(H1);
                ph[ksv][hh]     = *reinterpret_cast<uint32_t*>(&H0);
                ph[ksv][hh + 1] = *reinterpret_cast<uint32_t*>(&H1);
            }

            // ---- O += P V (16x128), fp16, single-V ----
#pragma unroll
            for (int ksv = 0; ksv < 4; ++ksv) {
#pragma unroll
                for (int p = 0; p < 8; p++) {
                    uint32_t v4[4];
                    ldm4(v4, aV + p * 16 * PV * 2 + ksv * 32);
                    mma16816h(o[2 * p],     ph[ksv], &v4[0]);
                    mma16816h(o[2 * p + 1], ph[ksv], &v4[2]);
                }
            }
        }

        // ---- slice epilogue: l reduce + partial writes ----
        lsumA += __shfl_xor_sync(0xffffffffu, lsumA, 1);
        lsumA += __shfl_xor_sync(0xffffffffu, lsumA, 2);
        lsumB += __shfl_xor_sync(0xffffffffu, lsumB, 1);
        lsumB += __shfl_xor_sync(0xffffffffu, lsumB, 2);
        if (tc == 0) {
            g_pl[slot][row_a] = lsumA;
            g_pl[slot][row_b] = lsumB;
        }
        float* po = g_po[slot];
#pragma unroll
        for (int ni = 0; ni < 16; ni++) {
            const int col = ni * 8 + tc * 2;
            *(float2*)&po[row_a * CC + col] = make_float2(o[ni][0], o[ni][1]);
            *(float2*)&po[row_b * CC + col] = make_float2(o[ni][2], o[ni][3]);
        }

        // ---- fused combine: last-arriving CTA for this (b,qt) finishes it ----
        __threadfence();
        __syncthreads();
        if (tid == 0) {
            int old = atomicAdd(&g_done[b * QT_N + qt], 1);
            *s_flag = (old == ns - 1) ? 1 : 0;
        }
        __syncthreads();
        if (*s_flag) {
            __threadfence();
            const int s0 = (b * QT_N + qt) * MAXSUB;
            float* invl = (float*)(smem + SM_INVL);
            for (int r = tid; r < 128; r += 256) {
                float ssum = 0.0f;
                for (int u = 0; u < ns; u++) ssum += g_pl[s0 + u][r];
                invl[r] = 1.0f / ssum;
            }
            __syncthreads();
            float* dst = out + (size_t)(b * TT + qt * BQ) * CC;
#pragma unroll 2
            for (int f = tid; f < BQ * CC / 4; f += 256) {
                const int row = f >> 5;
                float4 a = *(const float4*)&g_po[s0][f * 4];
                for (int u = 1; u < ns; u++) {
                    float4 v = *(const float4*)&g_po[s0 + u][f * 4];
                    a.x += v.x; a.y += v.y; a.z += v.z; a.w += v.w;
                }
                const float inv = invl[row];
                a.x *= inv; a.y *= inv; a.z *= inv; a.w *= inv;
                *(float4*)&dst[f * 4] = a;
            }
        }

        // ---- pop next slice ----
        if (tid == 0) *s_next = atomicAdd(&g_ctr, 1);
        __syncthreads();
        slice = *s_next;
    }
}

// ---------------------------------------------------------------------------
extern "C" void kernel_launch(void* const* d_in, const int* in_sizes, int n_in,
                              void* d_out, int out_size)
{
    const float* x  = (const float*)d_in[0];
    const float* Wq = (const float*)d_in[1];
    const float* Wk = (const float*)d_in[2];
    const float* Wv = (const float*)d_in[3];
    float* out = (float*)d_out;

    cudaFuncSetAttribute(flash_attn,
                         cudaFuncAttributeMaxDynamicSharedMemorySize,
                         FLASH_SMEM);
    cudaFuncSetAttribute(qkv_proj_mma,
                         cudaFuncAttributeMaxDynamicSharedMemorySize,
                         PROJ_SMEM);

    qkv_proj_mma<<<dim3(BT / 128, 3), 256, PROJ_SMEM>>>(x, Wq, Wk, Wv);
    flash_attn<<<NCTA, 256, FLASH_SMEM>>>(out);
}

// round 14
// speedup vs baseline: 1.3966x; 1.2076x over previous
#include <cuda_runtime.h>
#include <cuda_bf16.h>
#include <cuda_fp16.h>
#include <cstdint>

// CausalSelfAttention: B=4, T=4096, C=128, fp32 in/out.
// K1: tensorized QKV projection (mma.sync bf16 hi/lo x3-term GEMM).
//     Outputs: Q fp16 hi/lo (pre-scaled), K single fp16, V single fp16 (transposed).
// K2: persistent flash attention: warp-private 16-row tiles;
//     S = fp16 2-term (Qh*K + Ql*K, Q exact to 2^-22, K rounded 2^-11);
//     PV = fp16 single-V (l summed over rounded Ph); cp.async staged Q +
//     double-buffered K/V; split-KV queue (CH=6); fused per-tile combine.

#define BB 4
#define TT 4096
#define CC 128
#define BT (BB*TT)
#define QT_N 32
#define SCALE_L2E (0.08838834764831845f * 1.4426950408889634f)

#define BQ 128
#define BKT 64
#define CH 6
#define MAXSUB 11
#define NSLICES 748     // 4 * sum_qt ceil((2qt+2)/6)
#define NCTA 148

// ---------------- scratch (device globals; no cudaMalloc) -------------------
__device__ __align__(256) __half g_qh[BT*CC], g_ql[BT*CC];   // [t][c] fp16 hi/lo
__device__ __align__(256) __half g_k[BT*CC];                 // [t][c] fp16
__device__ __align__(256) __half g_v[BB*CC*TT];              // [b][c][t] fp16
__device__ __align__(256) float g_po[BB*QT_N*MAXSUB][BQ*CC];
__device__ __align__(256) float g_pl[BB*QT_N*MAXSUB][BQ];
__device__ int g_ctr;
__device__ int g_done[BB*QT_N];

// ---------------- helpers ---------------------------------------------------
__device__ __forceinline__ uint32_t smem_u32(const void* p) {
    uint32_t a;
    asm("{ .reg .u64 t; cvta.to.shared.u64 t, %1; cvt.u32.u64 %0, t; }"
        : "=r"(a) : "l"(p));
    return a;
}
__device__ __forceinline__ void ldm4(uint32_t* r, uint32_t a) {
    asm volatile("ldmatrix.sync.aligned.m8n8.x4.shared.b16 {%0,%1,%2,%3}, [%4];"
        : "=r"(r[0]), "=r"(r[1]), "=r"(r[2]), "=r"(r[3]) : "r"(a));
}
__device__ __forceinline__ void mma16816(float* c, const uint32_t* a,
                                         const uint32_t* b) {
    asm("mma.sync.aligned.m16n8k16.row.col.f32.bf16.bf16.f32 "
        "{%0,%1,%2,%3}, {%4,%5,%6,%7}, {%8,%9}, {%0,%1,%2,%3};"
        : "+f"(c[0]), "+f"(c[1]), "+f"(c[2]), "+f"(c[3])
        : "r"(a[0]), "r"(a[1]), "r"(a[2]), "r"(a[3]), "r"(b[0]), "r"(b[1]));
}
__device__ __forceinline__ void mma16816h(float* c, const uint32_t* a,
                                          const uint32_t* b) {
    asm("mma.sync.aligned.m16n8k16.row.col.f32.f16.f16.f32 "
        "{%0,%1,%2,%3}, {%4,%5,%6,%7}, {%8,%9}, {%0,%1,%2,%3};"
        : "+f"(c[0]), "+f"(c[1]), "+f"(c[2]), "+f"(c[3])
        : "r"(a[0]), "r"(a[1]), "r"(a[2]), "r"(a[3]), "r"(b[0]), "r"(b[1]));
}
#define CP_ASYNC16(dst, src) \
    asm volatile("cp.async.cg.shared.global [%0], [%1], 16;" \
                 :: "r"(dst), "l"(src))
#define CP_COMMIT() asm volatile("cp.async.commit_group;" ::: "memory")
#define CP_WAIT(n)  asm volatile("cp.async.wait_group %0;" :: "n"(n) : "memory")

// ---------------------------------------------------------------------------
// K1: tensorized QKV projection. GEMM in bf16 hi/lo (residual 2^-17, fine for
// all outputs). Epilogues: Q -> fp16 hi/lo scaled; K -> fp16; V -> fp16^T.
// ---------------------------------------------------------------------------
#define PX 136
#define SMX_H 0
#define SMX_L (SMX_H + 128*PX*2)
#define SMW_H (SMX_L + 128*PX*2)
#define SMW_L (SMW_H + 128*PX*2)
#define PROJ_SMEM (SMW_L + 128*PX*2)
#define PSTG 129

__global__ __launch_bounds__(256, 1) void qkv_proj_mma(
    const float* __restrict__ x,
    const float* __restrict__ Wq,
    const float* __restrict__ Wk,
    const float* __restrict__ Wv)
{
    extern __shared__ char smem[];
    const uint32_t sb = smem_u32(smem);
    const int widx = blockIdx.y;
    const float* __restrict__ W = (widx == 0) ? Wq : ((widx == 1) ? Wk : Wv);
    const int row0 = blockIdx.x * 128;
    const int tid = threadIdx.x, lane = tid & 31, wid = tid >> 5;
    const int wm = wid & 3, wn = wid >> 2;
    const int gr = lane >> 2, tc = lane & 3;

    if (blockIdx.x == 0 && widx == 0) {
        if (tid == 0) g_ctr = NCTA;
        if (tid < BB * QT_N) g_done[tid] = 0;
    }

#pragma unroll
    for (int f = tid; f < 128 * 32; f += 256) {
        const int r = f >> 5, c4 = (f & 31) * 4;
        float4 v = *(const float4*)&x[(size_t)(row0 + r) * CC + c4];
        __nv_bfloat162 h0 = __floats2bfloat162_rn(v.x, v.y);
        __nv_bfloat162 h1 = __floats2bfloat162_rn(v.z, v.w);
        __nv_bfloat162 l0 = __floats2bfloat162_rn(v.x - __low2float(h0),
                                                  v.y - __high2float(h0));
        __nv_bfloat162 l1 = __floats2bfloat162_rn(v.z - __low2float(h1),
                                                  v.w - __high2float(h1));
        const int o = (r * PX + c4) * 2;
        *(uint32_t*)(smem + SMX_H + o)     = *reinterpret_cast<uint32_t*>(&h0);
        *(uint32_t*)(smem + SMX_H + o + 4) = *reinterpret_cast<uint32_t*>(&h1);
        *(uint32_t*)(smem + SMX_L + o)     = *reinterpret_cast<uint32_t*>(&l0);
        *(uint32_t*)(smem + SMX_L + o + 4) = *reinterpret_cast<uint32_t*>(&l1);
    }
#pragma unroll
    for (int f = tid; f < 128 * 32; f += 256) {
        const int d = f >> 5, c4 = (f & 31) * 4;
        float4 v = *(const float4*)&W[(size_t)d * CC + c4];
        __nv_bfloat162 h0 = __floats2bfloat162_rn(v.x, v.y);
        __nv_bfloat162 h1 = __floats2bfloat162_rn(v.z, v.w);
        __nv_bfloat162 l0 = __floats2bfloat162_rn(v.x - __low2float(h0),
                                                  v.y - __high2float(h0));
        __nv_bfloat162 l1 = __floats2bfloat162_rn(v.z - __low2float(h1),
                                                  v.w - __high2float(h1));
        const int o = (d * PX + c4) * 2;
        *(uint32_t*)(smem + SMW_H + o)     = *reinterpret_cast<uint32_t*>(&h0);
        *(uint32_t*)(smem + SMW_H + o + 4) = *reinterpret_cast<uint32_t*>(&h1);
        *(uint32_t*)(smem + SMW_L + o)     = *reinterpret_cast<uint32_t*>(&l0);
        *(uint32_t*)(smem + SMW_L + o + 4) = *reinterpret_cast<uint32_t*>(&l1);
    }
    __syncthreads();

    const int lr = lane & 15, lh = lane >> 4;
    const int bn = (lane & 7) + ((lane >> 4) << 3);
    const int bk8 = ((lane >> 3) & 1) << 3;
    const uint32_t aXh = sb + SMX_H + (((wm * 32 + lr) * PX) + lh * 8) * 2;
    const uint32_t aXl = aXh + (SMX_L - SMX_H);
    const uint32_t aWh = sb + SMW_H + (((wn * 64 + bn) * PX) + bk8) * 2;
    const uint32_t aWl = aWh + (SMW_L - SMW_H);

    float acc[2][8][4];
#pragma unroll
    for (int mi = 0; mi < 2; mi++)
#pragma unroll
        for (int ni = 0; ni < 8; ni++)
#pragma unroll
            for (int e = 0; e < 4; e++) acc[mi][ni][e] = 0.0f;

#pragma unroll
    for (int ks = 0; ks < 8; ++ks) {
        uint32_t ah[2][4], al[2][4], bh[8][2], bl[8][2];
        ldm4(ah[0], aXh + ks * 32);
        ldm4(ah[1], aXh + 16 * PX * 2 + ks * 32);
        ldm4(al[0], aXl + ks * 32);
        ldm4(al[1], aXl + 16 * PX * 2 + ks * 32);
#pragma unroll
        for (int p = 0; p < 4; p++) {
            ldm4(&bh[2 * p][0], aWh + p * 16 * PX * 2 + ks * 32);
            ldm4(&bl[2 * p][0], aWl + p * 16 * PX * 2 + ks * 32);
        }
#pragma unroll
        for (int mi = 0; mi < 2; mi++)
#pragma unroll
            for (int ni = 0; ni < 8; ni++) {
                mma16816(acc[mi][ni], ah[mi], bh[ni]);
                mma16816(acc[mi][ni], ah[mi], bl[ni]);
                mma16816(acc[mi][ni], al[mi], bh[ni]);
            }
    }

    if (widx == 0) {
        // ---- Q: fp16 hi/lo, pre-scaled ----
#pragma unroll
        for (int mi = 0; mi < 2; mi++)
#pragma unroll
            for (int half = 0; half < 2; half++) {
                const int row = wm * 32 + mi * 16 + gr + half * 8;
                const size_t rb = (size_t)(row0 + row) * CC;
#pragma unroll
                for (int ni = 0; ni < 8; ni++) {
                    const int col = wn * 64 + ni * 8 + tc * 2;
                    float y0 = acc[mi][ni][half * 2 + 0] * SCALE_L2E;
                    float y1 = acc[mi][ni][half * 2 + 1] * SCALE_L2E;
                    __half2 H = __floats2half2_rn(y0, y1);
                    __half2 L = __floats2half2_rn(y0 - __low2float(H),
                                                  y1 - __high2float(H));
                    *(uint32_t*)&g_qh[rb + col] = *reinterpret_cast<uint32_t*>(&H);
                    *(uint32_t*)&g_ql[rb + col] = *reinterpret_cast<uint32_t*>(&L);
                }
            }
    } else if (widx == 1) {
        // ---- K: single fp16, row-major ----
#pragma unroll
        for (int mi = 0; mi < 2; mi++)
#pragma unroll
            for (int half = 0; half < 2; half++) {
                const int row = wm * 32 + mi * 16 + gr + half * 8;
                const size_t rb = (size_t)(row0 + row) * CC;
#pragma unroll
                for (int ni = 0; ni < 8; ni++) {
                    const int col = wn * 64 + ni * 8 + tc * 2;
                    __half2 H = __floats2half2_rn(acc[mi][ni][half * 2 + 0],
                                                  acc[mi][ni][half * 2 + 1]);
                    *(uint32_t*)&g_k[rb + col] = *reinterpret_cast<uint32_t*>(&H);
                }
            }
    } else {
        // ---- V: stage fp32, transposed single-fp16 store ----
        __syncthreads();
        float* stg = (float*)smem;
#pragma unroll
        for (int mi = 0; mi < 2; mi++)
#pragma unroll
            for (int half = 0; half < 2; half++) {
                const int row = wm * 32 + mi * 16 + gr + half * 8;
#pragma unroll
                for (int ni = 0; ni < 8; ni++) {
                    const int col = wn * 64 + ni * 8 + tc * 2;
                    stg[row * PSTG + col]     = acc[mi][ni][half * 2 + 0];
                    stg[row * PSTG + col + 1] = acc[mi][ni][half * 2 + 1];
                }
            }
        __syncthreads();
        const int b = row0 >> 12, t0 = row0 & (TT - 1);
        __half* vv = g_v + (size_t)b * CC * TT + t0;
#pragma unroll 1
        for (int c = wid; c < 128; c += 8) {
            float v[4];
#pragma unroll
            for (int i = 0; i < 4; i++)
                v[i] = stg[(lane * 4 + i) * PSTG + c];
            __half2 h0 = __floats2half2_rn(v[0], v[1]);
            __half2 h1 = __floats2half2_rn(v[2], v[3]);
            uint2 Hp = make_uint2(*reinterpret_cast<uint32_t*>(&h0),
                                  *reinterpret_cast<uint32_t*>(&h1));
            *(uint2*)&vv[(size_t)c * TT + lane * 4] = Hp;
        }
    }
}

// ---------------------------------------------------------------------------
// K2: persistent flash attention + fused combine. K and V single fp16.
// ---------------------------------------------------------------------------
#define PQ 136
#define PK 136
#define PV 72
#define SM_QH 0
#define SM_QL (128*PQ*2)                 // 34816
#define SM_KV (2*128*PQ*2)               // 69632
#define KBUF  (64*PK*2)                  // 17408 (single K)
#define OFF_K 0
#define OFF_V KBUF
#define BUFSZ (KBUF + 128*PV*2)          // 35840
#define SM_NEXT (SM_KV + 2*BUFSZ)        // +0 next, +4 flag
#define SM_INVL (SM_NEXT + 16)
#define FLASH_SMEM (SM_INVL + 128*4)

__device__ __forceinline__ void prefetch_kv(uint32_t buf, int b, int j, int tid)
{
    const __half* kk = g_k + (size_t)(b * TT + j * BKT) * CC;
#pragma unroll
    for (int u = 0; u < 4; u++) {
        const int f = tid + u * 256, r = f >> 4, c8 = (f & 15) << 3;
        CP_ASYNC16(buf + OFF_K + (r * PK + c8) * 2, kk + r * CC + c8);
    }
    const __half* vv = g_v + (size_t)b * CC * TT + j * BKT;
#pragma unroll
    for (int u = 0; u < 4; u++) {
        const int f = tid + u * 256, d = f >> 3, c8 = (f & 7) << 3;
        CP_ASYNC16(buf + OFF_V + (d * PV + c8) * 2, vv + (size_t)d * TT + c8);
    }
}

__global__ __launch_bounds__(256, 1) void flash_attn(float* __restrict__ out)
{
    extern __shared__ char smem[];
    const uint32_t sb = smem_u32(smem);
    const int tid = threadIdx.x, lane = tid & 31, wid = tid >> 5;
    const int gr = lane >> 2, tc = lane & 3;

    const int lr = lane & 15, lh = lane >> 4;
    const int bn = (lane & 7) + ((lane >> 4) << 3);
    const int bk8 = ((lane >> 3) & 1) << 3;

    const uint32_t aQh = sb + SM_QH + (((wid * 16 + lr) * PQ) + lh * 8) * 2;
    const uint32_t aQl = aQh + (SM_QL - SM_QH);
    const uint32_t aKrel = (bn * PK + bk8) * 2;
    const uint32_t aVrel = (bn * PV + bk8) * 2;

    const int row_a = wid * 16 + gr;
    const int row_b = row_a + 8;
    int* s_next = (int*)(smem + SM_NEXT);
    int* s_flag = (int*)(smem + SM_NEXT + 4);

    int slice = blockIdx.x;
    while (slice < NSLICES) {
        // ---- decode slice -> (b, qt, sub, kv0, kv1, ns) ----
        int rem = slice, qt = 31, ns = 1;
#pragma unroll 1
        for (qt = 31; qt > 0; --qt) {
            ns = (2 * qt + 2 + CH - 1) / CH;
            if (rem < 4 * ns) break;
            rem -= 4 * ns;
        }
        if (qt == 0) ns = 1;
        const int b = rem & 3, sub = rem >> 2;
        const int it = 2 * qt + 2;
        const int base = it / ns, r2 = it - base * ns;
        const int kv0 = sub * base + (sub < r2 ? sub : r2);
        const int kv1 = kv0 + base + (sub < r2 ? 1 : 0);
        const int slot = (b * QT_N + qt) * MAXSUB + sub;

        // ---- prologue: cp.async Q (group 1) then KV0 (group 2) ----
        {
            const __half* qh = g_qh + (size_t)(b * TT + qt * BQ) * CC;
            const __half* ql = g_ql + (size_t)(b * TT + qt * BQ) * CC;
#pragma unroll
            for (int u = 0; u < 8; u++) {
                const int f = tid + u * 256, r = f >> 4, c8 = (f & 15) << 3;
                const uint32_t o = sb + SM_QH + (r * PQ + c8) * 2;
                CP_ASYNC16(o, qh + r * CC + c8);
                CP_ASYNC16(o + (SM_QL - SM_QH), ql + r * CC + c8);
            }
        }
        CP_COMMIT();
        prefetch_kv(sb + SM_KV, b, kv0, tid);
        CP_COMMIT();
        CP_WAIT(1);                      // Q complete; KV0 may be in flight
        __syncthreads();                 // Q visible to all warps
        uint32_t qah[8][4];
#pragma unroll
        for (int ks = 0; ks < 8; ++ks)
            ldm4(qah[ks], aQh + ks * 32);

        float o[16][4];
#pragma unroll
        for (int ni = 0; ni < 16; ni++)
#pragma unroll
            for (int e = 0; e < 4; e++) o[ni][e] = 0.0f;
        float lsumA = 0.0f, lsumB = 0.0f;

        int cur = 0;
#pragma unroll 1
        for (int j = kv0; j < kv1; ++j, cur ^= 1) {
            __syncthreads();             // prev-buffer reads complete
            if (j + 1 < kv1) {
                prefetch_kv(sb + SM_KV + (cur ^ 1) * BUFSZ, b, j + 1, tid);
                CP_COMMIT();
                CP_WAIT(1);              // tile j complete, j+1 in flight
            } else {
                CP_WAIT(0);
            }
            __syncthreads();             // tile j visible

            const uint32_t kb = sb + SM_KV + cur * BUFSZ;
            const uint32_t aK = kb + OFF_K + aKrel;
            const uint32_t aV = kb + OFF_V + aVrel;

            // ---- S = Q K^T (16x64), fp16 2-term: Qh*K + Ql*K ----
            float s[8][4];
#pragma unroll
            for (int ni = 0; ni < 8; ni++)
#pragma unroll
                for (int e = 0; e < 4; e++) s[ni][e] = 0.0f;

#pragma unroll
            for (int ks = 0; ks < 8; ++ks) {
                uint32_t qal4[4];
                ldm4(qal4, aQl + ks * 32);
#pragma unroll
                for (int p = 0; p < 4; p++) {
                    uint32_t k4[4];
                    ldm4(k4, aK + p * 16 * PK * 2 + ks * 32);
                    mma16816h(s[2 * p],     qah[ks], &k4[0]);
                    mma16816h(s[2 * p + 1], qah[ks], &k4[2]);
                    mma16816h(s[2 * p],     qal4,    &k4[0]);
                    mma16816h(s[2 * p + 1], qal4,    &k4[2]);
                }
            }

            // ---- softmax -> fp16 Ph A-fragments; l over rounded Ph ----
            const int srel = j * BKT - qt * BQ;
            uint32_t ph[4][4];
#pragma unroll
            for (int ni = 0; ni < 8; ni++) {
                const int ksv = ni >> 1, hh = (ni & 1) * 2;
                const int col = srel + ni * 8 + tc * 2;
                float p0 = (col     <= row_a) ? exp2f(s[ni][0]) : 0.0f;
                float p1 = (col + 1 <= row_a) ? exp2f(s[ni][1]) : 0.0f;
                float p2 = (col     <= row_b) ? exp2f(s[ni][2]) : 0.0f;
                float p3 = (col + 1 <= row_b) ? exp2f(s[ni][3]) : 0.0f;
                __half2 H0 = __floats2half2_rn(p0, p1);
                __half2 H1 = __floats2half2_rn(p2, p3);
                lsumA += __low2float(H0) + __high2float(H0);
                lsumB += __low2float(H1) + __high2float(H1);
                ph[ksv][hh]     = *reinterpret_cast<uint32_t*>(&H0);
                ph[ksv][hh + 1] = *reinterpret_cast<uint32_t*>(&H1);
            }

            // ---- O += P V (16x128), fp16, single-V ----
#pragma unroll
            for (int ksv = 0; ksv < 4; ++ksv) {
#pragma unroll
                for (int p = 0; p < 8; p++) {
                    uint32_t v4[4];
                    ldm4(v4, aV + p * 16 * PV * 2 + ksv * 32);
                    mma16816h(o[2 * p],     ph[ksv], &v4[0]);
                    mma16816h(o[2 * p + 1], ph[ksv], &v4[2]);
                }
            }
        }

        // ---- slice epilogue: l reduce + partial writes ----
        lsumA += __shfl_xor_sync(0xffffffffu, lsumA, 1);
        lsumA += __shfl_xor_sync(0xffffffffu, lsumA, 2);
        lsumB += __shfl_xor_sync(0xffffffffu, lsumB, 1);
        lsumB += __shfl_xor_sync(0xffffffffu, lsumB, 2);
        if (tc == 0) {
            g_pl[slot][row_a] = lsumA;
            g_pl[slot][row_b] = lsumB;
        }
        float* po = g_po[slot];
#pragma unroll
        for (int ni = 0; ni < 16; ni++) {
            const int col = ni * 8 + tc * 2;
            *(float2*)&po[row_a * CC + col] = make_float2(o[ni][0], o[ni][1]);
            *(float2*)&po[row_b * CC + col] = make_float2(o[ni][2], o[ni][3]);
        }

        // ---- fused combine: last-arriving CTA for this (b,qt) finishes it ----
        __threadfence();
        __syncthreads();
        if (tid == 0) {
            int old = atomicAdd(&g_done[b * QT_N + qt], 1);
            *s_flag = (old == ns - 1) ? 1 : 0;
        }
        __syncthreads();
        if (*s_flag) {
            __threadfence();
            const int s0 = (b * QT_N + qt) * MAXSUB;
            float* invl = (float*)(smem + SM_INVL);
            for (int r = tid; r < 128; r += 256) {
                float ssum = 0.0f;
                for (int u = 0; u < ns; u++) ssum += g_pl[s0 + u][r];
                invl[r] = 1.0f / ssum;
            }
            __syncthreads();
            float* dst = out + (size_t)(b * TT + qt * BQ) * CC;
#pragma unroll 2
            for (int f = tid; f < BQ * CC / 4; f += 256) {
                const int row = f >> 5;
                float4 a = *(const float4*)&g_po[s0][f * 4];
                for (int u = 1; u < ns; u++) {
                    float4 v = *(const float4*)&g_po[s0 + u][f * 4];
                    a.x += v.x; a.y += v.y; a.z += v.z; a.w += v.w;
                }
                const float inv = invl[row];
                a.x *= inv; a.y *= inv; a.z *= inv; a.w *= inv;
                *(float4*)&dst[f * 4] = a;
            }
        }

        // ---- pop next slice ----
        if (tid == 0) *s_next = atomicAdd(&g_ctr, 1);
        __syncthreads();
        slice = *s_next;
    }
}

// ---------------------------------------------------------------------------
extern "C" void kernel_launch(void* const* d_in, const int* in_sizes, int n_in,
                              void* d_out, int out_size)
{
    const float* x  = (const float*)d_in[0];
    const float* Wq = (const float*)d_in[1];
    const float* Wk = (const float*)d_in[2];
    const float* Wv = (const float*)d_in[3];
    float* out = (float*)d_out;

    cudaFuncSetAttribute(flash_attn,
                         cudaFuncAttributeMaxDynamicSharedMemorySize,
                         FLASH_SMEM);
    cudaFuncSetAttribute(qkv_proj_mma,
                         cudaFuncAttributeMaxDynamicSharedMemorySize,
                         PROJ_SMEM);

    qkv_proj_mma<<<dim3(BT / 128, 3), 256, PROJ_SMEM>>>(x, Wq, Wk, Wv);
    flash_attn<<<NCTA, 256, FLASH_SMEM>>>(out);
}

// round 15
// speedup vs baseline: 1.6392x; 1.1737x over previous
#include <cuda_runtime.h>
#include <cuda_bf16.h>
#include <cuda_fp16.h>
#include <cstdint>

// CausalSelfAttention: B=4, T=4096, C=128, fp32 in/out.
// K1: tensorized QKV projection (mma.sync bf16 hi/lo x3-term GEMM).
//     Outputs: Q single fp16 (pre-scaled), K single fp16, V single fp16 (transposed).
// K2: persistent flash attention: warp-private 16-row tiles;
//     S = fp16 single-term Q*K; PV = fp16 single-V (l summed over rounded Ph);
//     cp.async staged Q + double-buffered K/V; split-KV queue (CH=6);
//     fused per-tile combine. Fast path skips causal compares on
//     fully-unmasked tiles.

#define BB 4
#define TT 4096
#define CC 128
#define BT (BB*TT)
#define QT_N 32
#define SCALE_L2E (0.08838834764831845f * 1.4426950408889634f)

#define BQ 128
#define BKT 64
#define CH 6
#define MAXSUB 11
#define NSLICES 748     // 4 * sum_qt ceil((2qt+2)/6)
#define NCTA 148

// ---------------- scratch (device globals; no cudaMalloc) -------------------
__device__ __align__(256) __half g_q[BT*CC];                 // [t][c] fp16, *SCALE_L2E
__device__ __align__(256) __half g_k[BT*CC];                 // [t][c] fp16
__device__ __align__(256) __half g_v[BB*CC*TT];              // [b][c][t] fp16
__device__ __align__(256) float g_po[BB*QT_N*MAXSUB][BQ*CC];
__device__ __align__(256) float g_pl[BB*QT_N*MAXSUB][BQ];
__device__ int g_ctr;
__device__ int g_done[BB*QT_N];

// ---------------- helpers ---------------------------------------------------
__device__ __forceinline__ uint32_t smem_u32(const void* p) {
    uint32_t a;
    asm("{ .reg .u64 t; cvta.to.shared.u64 t, %1; cvt.u32.u64 %0, t; }"
        : "=r"(a) : "l"(p));
    return a;
}
__device__ __forceinline__ void ldm4(uint32_t* r, uint32_t a) {
    asm volatile("ldmatrix.sync.aligned.m8n8.x4.shared.b16 {%0,%1,%2,%3}, [%4];"
        : "=r"(r[0]), "=r"(r[1]), "=r"(r[2]), "=r"(r[3]) : "r"(a));
}
__device__ __forceinline__ void mma16816(float* c, const uint32_t* a,
                                         const uint32_t* b) {
    asm("mma.sync.aligned.m16n8k16.row.col.f32.bf16.bf16.f32 "
        "{%0,%1,%2,%3}, {%4,%5,%6,%7}, {%8,%9}, {%0,%1,%2,%3};"
        : "+f"(c[0]), "+f"(c[1]), "+f"(c[2]), "+f"(c[3])
        : "r"(a[0]), "r"(a[1]), "r"(a[2]), "r"(a[3]), "r"(b[0]), "r"(b[1]));
}
__device__ __forceinline__ void mma16816h(float* c, const uint32_t* a,
                                          const uint32_t* b) {
    asm("mma.sync.aligned.m16n8k16.row.col.f32.f16.f16.f32 "
        "{%0,%1,%2,%3}, {%4,%5,%6,%7}, {%8,%9}, {%0,%1,%2,%3};"
        : "+f"(c[0]), "+f"(c[1]), "+f"(c[2]), "+f"(c[3])
        : "r"(a[0]), "r"(a[1]), "r"(a[2]), "r"(a[3]), "r"(b[0]), "r"(b[1]));
}
#define CP_ASYNC16(dst, src) \
    asm volatile("cp.async.cg.shared.global [%0], [%1], 16;" \
                 :: "r"(dst), "l"(src))
#define CP_COMMIT() asm volatile("cp.async.commit_group;" ::: "memory")
#define CP_WAIT(n)  asm volatile("cp.async.wait_group %0;" :: "n"(n) : "memory")

// ---------------------------------------------------------------------------
// K1: tensorized QKV projection. GEMM in bf16 hi/lo (residual 2^-17).
// Epilogues: Q -> fp16 scaled; K -> fp16; V -> fp16 transposed.
// ---------------------------------------------------------------------------
#define PX 136
#define SMX_H 0
#define SMX_L (SMX_H + 128*PX*2)
#define SMW_H (SMX_L + 128*PX*2)
#define SMW_L (SMW_H + 128*PX*2)
#define PROJ_SMEM (SMW_L + 128*PX*2)
#define PSTG 129

__global__ __launch_bounds__(256, 1) void qkv_proj_mma(
    const float* __restrict__ x,
    const float* __restrict__ Wq,
    const float* __restrict__ Wk,
    const float* __restrict__ Wv)
{
    extern __shared__ char smem[];
    const uint32_t sb = smem_u32(smem);
    const int widx = blockIdx.y;
    const float* __restrict__ W = (widx == 0) ? Wq : ((widx == 1) ? Wk : Wv);
    const int row0 = blockIdx.x * 128;
    const int tid = threadIdx.x, lane = tid & 31, wid = tid >> 5;
    const int wm = wid & 3, wn = wid >> 2;
    const int gr = lane >> 2, tc = lane & 3;

    if (blockIdx.x == 0 && widx == 0) {
        if (tid == 0) g_ctr = NCTA;
        if (tid < BB * QT_N) g_done[tid] = 0;
    }

#pragma unroll
    for (int f = tid; f < 128 * 32; f += 256) {
        const int r = f >> 5, c4 = (f & 31) * 4;
        float4 v = *(const float4*)&x[(size_t)(row0 + r) * CC + c4];
        __nv_bfloat162 h0 = __floats2bfloat162_rn(v.x, v.y);
        __nv_bfloat162 h1 = __floats2bfloat162_rn(v.z, v.w);
        __nv_bfloat162 l0 = __floats2bfloat162_rn(v.x - __low2float(h0),
                                                  v.y - __high2float(h0));
        __nv_bfloat162 l1 = __floats2bfloat162_rn(v.z - __low2float(h1),
                                                  v.w - __high2float(h1));
        const int o = (r * PX + c4) * 2;
        *(uint32_t*)(smem + SMX_H + o)     = *reinterpret_cast<uint32_t*>(&h0);
        *(uint32_t*)(smem + SMX_H + o + 4) = *reinterpret_cast<uint32_t*>(&h1);
        *(uint32_t*)(smem + SMX_L + o)     = *reinterpret_cast<uint32_t*>(&l0);
        *(uint32_t*)(smem + SMX_L + o + 4) = *reinterpret_cast<uint32_t*>(&l1);
    }
#pragma unroll
    for (int f = tid; f < 128 * 32; f += 256) {
        const int d = f >> 5, c4 = (f & 31) * 4;
        float4 v = *(const float4*)&W[(size_t)d * CC + c4];
        __nv_bfloat162 h0 = __floats2bfloat162_rn(v.x, v.y);
        __nv_bfloat162 h1 = __floats2bfloat162_rn(v.z, v.w);
        __nv_bfloat162 l0 = __floats2bfloat162_rn(v.x - __low2float(h0),
                                                  v.y - __high2float(h0));
        __nv_bfloat162 l1 = __floats2bfloat162_rn(v.z - __low2float(h1),
                                                  v.w - __high2float(h1));
        const int o = (d * PX + c4) * 2;
        *(uint32_t*)(smem + SMW_H + o)     = *reinterpret_cast<uint32_t*>(&h0);
        *(uint32_t*)(smem + SMW_H + o + 4) = *reinterpret_cast<uint32_t*>(&h1);
        *(uint32_t*)(smem + SMW_L + o)     = *reinterpret_cast<uint32_t*>(&l0);
        *(uint32_t*)(smem + SMW_L + o + 4) = *reinterpret_cast<uint32_t*>(&l1);
    }
    __syncthreads();

    const int lr = lane & 15, lh = lane >> 4;
    const int bn = (lane & 7) + ((lane >> 4) << 3);
    const int bk8 = ((lane >> 3) & 1) << 3;
    const uint32_t aXh = sb + SMX_H + (((wm * 32 + lr) * PX) + lh * 8) * 2;
    const uint32_t aXl = aXh + (SMX_L - SMX_H);
    const uint32_t aWh = sb + SMW_H + (((wn * 64 + bn) * PX) + bk8) * 2;
    const uint32_t aWl = aWh + (SMW_L - SMW_H);

    float acc[2][8][4];
#pragma unroll
    for (int mi = 0; mi < 2; mi++)
#pragma unroll
        for (int ni = 0; ni < 8; ni++)
#pragma unroll
            for (int e = 0; e < 4; e++) acc[mi][ni][e] = 0.0f;

#pragma unroll
    for (int ks = 0; ks < 8; ++ks) {
        uint32_t ah[2][4], al[2][4], bh[8][2], bl[8][2];
        ldm4(ah[0], aXh + ks * 32);
        ldm4(ah[1], aXh + 16 * PX * 2 + ks * 32);
        ldm4(al[0], aXl + ks * 32);
        ldm4(al[1], aXl + 16 * PX * 2 + ks * 32);
#pragma unroll
        for (int p = 0; p < 4; p++) {
            ldm4(&bh[2 * p][0], aWh + p * 16 * PX * 2 + ks * 32);
            ldm4(&bl[2 * p][0], aWl + p * 16 * PX * 2 + ks * 32);
        }
#pragma unroll
        for (int mi = 0; mi < 2; mi++)
#pragma unroll
            for (int ni = 0; ni < 8; ni++) {
                mma16816(acc[mi][ni], ah[mi], bh[ni]);
                mma16816(acc[mi][ni], ah[mi], bl[ni]);
                mma16816(acc[mi][ni], al[mi], bh[ni]);
            }
    }

    if (widx < 2) {
        // ---- Q (scaled) / K: single fp16, row-major ----
        __half* dst = (widx == 0) ? g_q : g_k;
        const float sc = (widx == 0) ? SCALE_L2E : 1.0f;
#pragma unroll
        for (int mi = 0; mi < 2; mi++)
#pragma unroll
            for (int half = 0; half < 2; half++) {
                const int row = wm * 32 + mi * 16 + gr + half * 8;
                const size_t rb = (size_t)(row0 + row) * CC;
#pragma unroll
                for (int ni = 0; ni < 8; ni++) {
                    const int col = wn * 64 + ni * 8 + tc * 2;
                    __half2 H = __floats2half2_rn(acc[mi][ni][half * 2 + 0] * sc,
                                                  acc[mi][ni][half * 2 + 1] * sc);
                    *(uint32_t*)&dst[rb + col] = *reinterpret_cast<uint32_t*>(&H);
                }
            }
    } else {
        // ---- V: stage fp32, transposed single-fp16 store ----
        __syncthreads();
        float* stg = (float*)smem;
#pragma unroll
        for (int mi = 0; mi < 2; mi++)
#pragma unroll
            for (int half = 0; half < 2; half++) {
                const int row = wm * 32 + mi * 16 + gr + half * 8;
#pragma unroll
                for (int ni = 0; ni < 8; ni++) {
                    const int col = wn * 64 + ni * 8 + tc * 2;
                    stg[row * PSTG + col]     = acc[mi][ni][half * 2 + 0];
                    stg[row * PSTG + col + 1] = acc[mi][ni][half * 2 + 1];
                }
            }
        __syncthreads();
        const int b = row0 >> 12, t0 = row0 & (TT - 1);
        __half* vv = g_v + (size_t)b * CC * TT + t0;
#pragma unroll 1
        for (int c = wid; c < 128; c += 8) {
            float v[4];
#pragma unroll
            for (int i = 0; i < 4; i++)
                v[i] = stg[(lane * 4 + i) * PSTG + c];
            __half2 h0 = __floats2half2_rn(v[0], v[1]);
            __half2 h1 = __floats2half2_rn(v[2], v[3]);
            uint2 Hp = make_uint2(*reinterpret_cast<uint32_t*>(&h0),
                                  *reinterpret_cast<uint32_t*>(&h1));
            *(uint2*)&vv[(size_t)c * TT + lane * 4] = Hp;
        }
    }
}

// ---------------------------------------------------------------------------
// K2: persistent flash attention + fused combine. Q/K/V all single fp16.
// ---------------------------------------------------------------------------
#define PQ 136
#define PK 136
#define PV 72
#define SM_Q 0
#define SM_KV (128*PQ*2)                 // 34816
#define KBUF  (64*PK*2)                  // 17408
#define OFF_K 0
#define OFF_V KBUF
#define BUFSZ (KBUF + 128*PV*2)          // 35840
#define SM_NEXT (SM_KV + 2*BUFSZ)        // +0 next, +4 flag
#define SM_INVL (SM_NEXT + 16)
#define FLASH_SMEM (SM_INVL + 128*4)

__device__ __forceinline__ void prefetch_kv(uint32_t buf, int b, int j, int tid)
{
    const __half* kk = g_k + (size_t)(b * TT + j * BKT) * CC;
#pragma unroll
    for (int u = 0; u < 4; u++) {
        const int f = tid + u * 256, r = f >> 4, c8 = (f & 15) << 3;
        CP_ASYNC16(buf + OFF_K + (r * PK + c8) * 2, kk + r * CC + c8);
    }
    const __half* vv = g_v + (size_t)b * CC * TT + j * BKT;
#pragma unroll
    for (int u = 0; u < 4; u++) {
        const int f = tid + u * 256, d = f >> 3, c8 = (f & 7) << 3;
        CP_ASYNC16(buf + OFF_V + (d * PV + c8) * 2, vv + (size_t)d * TT + c8);
    }
}

__global__ __launch_bounds__(256, 1) void flash_attn(float* __restrict__ out)
{
    extern __shared__ char smem[];
    const uint32_t sb = smem_u32(smem);
    const int tid = threadIdx.x, lane = tid & 31, wid = tid >> 5;
    const int gr = lane >> 2, tc = lane & 3;

    const int lr = lane & 15, lh = lane >> 4;
    const int bn = (lane & 7) + ((lane >> 4) << 3);
    const int bk8 = ((lane >> 3) & 1) << 3;

    const uint32_t aQ = sb + SM_Q + (((wid * 16 + lr) * PQ) + lh * 8) * 2;
    const uint32_t aKrel = (bn * PK + bk8) * 2;
    const uint32_t aVrel = (bn * PV + bk8) * 2;

    const int row_a = wid * 16 + gr;
    const int row_b = row_a + 8;
    int* s_next = (int*)(smem + SM_NEXT);
    int* s_flag = (int*)(smem + SM_NEXT + 4);

    int slice = blockIdx.x;
    while (slice < NSLICES) {
        // ---- decode slice -> (b, qt, sub, kv0, kv1, ns) ----
        int rem = slice, qt = 31, ns = 1;
#pragma unroll 1
        for (qt = 31; qt > 0; --qt) {
            ns = (2 * qt + 2 + CH - 1) / CH;
            if (rem < 4 * ns) break;
            rem -= 4 * ns;
        }
        if (qt == 0) ns = 1;
        const int b = rem & 3, sub = rem >> 2;
        const int it = 2 * qt + 2;
        const int base = it / ns, r2 = it - base * ns;
        const int kv0 = sub * base + (sub < r2 ? sub : r2);
        const int kv1 = kv0 + base + (sub < r2 ? 1 : 0);
        const int slot = (b * QT_N + qt) * MAXSUB + sub;

        // ---- prologue: cp.async Q (group 1) then KV0 (group 2) ----
        {
            const __half* qq = g_q + (size_t)(b * TT + qt * BQ) * CC;
#pragma unroll
            for (int u = 0; u < 8; u++) {
                const int f = tid + u * 256, r = f >> 4, c8 = (f & 15) << 3;
                CP_ASYNC16(sb + SM_Q + (r * PQ + c8) * 2, qq + r * CC + c8);
            }
        }
        CP_COMMIT();
        prefetch_kv(sb + SM_KV, b, kv0, tid);
        CP_COMMIT();
        CP_WAIT(1);                      // Q complete; KV0 may be in flight
        __syncthreads();                 // Q visible to all warps
        uint32_t qah[8][4];
#pragma unroll
        for (int ks = 0; ks < 8; ++ks)
            ldm4(qah[ks], aQ + ks * 32);

        float o[16][4];
#pragma unroll
        for (int ni = 0; ni < 16; ni++)
#pragma unroll
            for (int e = 0; e < 4; e++) o[ni][e] = 0.0f;
        float lsumA = 0.0f, lsumB = 0.0f;

        int cur = 0;
#pragma unroll 1
        for (int j = kv0; j < kv1; ++j, cur ^= 1) {
            __syncthreads();             // prev-buffer reads complete
            if (j + 1 < kv1) {
                prefetch_kv(sb + SM_KV + (cur ^ 1) * BUFSZ, b, j + 1, tid);
                CP_COMMIT();
                CP_WAIT(1);              // tile j complete, j+1 in flight
            } else {
                CP_WAIT(0);
            }
            __syncthreads();             // tile j visible

            const uint32_t kb = sb + SM_KV + cur * BUFSZ;
            const uint32_t aK = kb + OFF_K + aKrel;
            const uint32_t aV = kb + OFF_V + aVrel;

            // ---- S = Q K^T (16x64), fp16 single-term ----
            float s[8][4];
#pragma unroll
            for (int ni = 0; ni < 8; ni++)
#pragma unroll
                for (int e = 0; e < 4; e++) s[ni][e] = 0.0f;

#pragma unroll
            for (int ks = 0; ks < 8; ++ks) {
#pragma unroll
                for (int p = 0; p < 4; p++) {
                    uint32_t k4[4];
                    ldm4(k4, aK + p * 16 * PK * 2 + ks * 32);
                    mma16816h(s[2 * p],     qah[ks], &k4[0]);
                    mma16816h(s[2 * p + 1], qah[ks], &k4[2]);
                }
            }

            // ---- softmax -> fp16 Ph A-fragments; l over rounded Ph ----
            const int srel = j * BKT - qt * BQ;
            uint32_t ph[4][4];
            if (srel + BKT - 1 <= row_a) {
                // fully unmasked for this warp's rows: no compares
#pragma unroll
                for (int ni = 0; ni < 8; ni++) {
                    const int ksv = ni >> 1, hh = (ni & 1) * 2;
                    float p0 = exp2f(s[ni][0]);
                    float p1 = exp2f(s[ni][1]);
                    float p2 = exp2f(s[ni][2]);
                    float p3 = exp2f(s[ni][3]);
                    __half2 H0 = __floats2half2_rn(p0, p1);
                    __half2 H1 = __floats2half2_rn(p2, p3);
                    lsumA += __low2float(H0) + __high2float(H0);
                    lsumB += __low2float(H1) + __high2float(H1);
                    ph[ksv][hh]     = *reinterpret_cast<uint32_t*>(&H0);
                    ph[ksv][hh + 1] = *reinterpret_cast<uint32_t*>(&H1);
                }
            } else {
#pragma unroll
                for (int ni = 0; ni < 8; ni++) {
                    const int ksv = ni >> 1, hh = (ni & 1) * 2;
                    const int col = srel + ni * 8 + tc * 2;
                    float p0 = (col     <= row_a) ? exp2f(s[ni][0]) : 0.0f;
                    float p1 = (col + 1 <= row_a) ? exp2f(s[ni][1]) : 0.0f;
                    float p2 = (col     <= row_b) ? exp2f(s[ni][2]) : 0.0f;
                    float p3 = (col + 1 <= row_b) ? exp2f(s[ni][3]) : 0.0f;
                    __half2 H0 = __floats2half2_rn(p0, p1);
                    __half2 H1 = __floats2half2_rn(p2, p3);
                    lsumA += __low2float(H0) + __high2float(H0);
                    lsumB += __low2float(H1) + __high2float(H1);
                    ph[ksv][hh]     = *reinterpret_cast<uint32_t*>(&H0);
                    ph[ksv][hh + 1] = *reinterpret_cast<uint32_t*>(&H1);
                }
            }

            // ---- O += P V (16x128), fp16, single-V ----
#pragma unroll
            for (int ksv = 0; ksv < 4; ++ksv) {
#pragma unroll
                for (int p = 0; p < 8; p++) {
                    uint32_t v4[4];
                    ldm4(v4, aV + p * 16 * PV * 2 + ksv * 32);
                    mma16816h(o[2 * p],     ph[ksv], &v4[0]);
                    mma16816h(o[2 * p + 1], ph[ksv], &v4[2]);
                }
            }
        }

        // ---- slice epilogue: l reduce + partial writes ----
        lsumA += __shfl_xor_sync(0xffffffffu, lsumA, 1);
        lsumA += __shfl_xor_sync(0xffffffffu, lsumA, 2);
        lsumB += __shfl_xor_sync(0xffffffffu, lsumB, 1);
        lsumB += __shfl_xor_sync(0xffffffffu, lsumB, 2);
        if (tc == 0) {
            g_pl[slot][row_a] = lsumA;
            g_pl[slot][row_b] = lsumB;
        }
        float* po = g_po[slot];
#pragma unroll
        for (int ni = 0; ni < 16; ni++) {
            const int col = ni * 8 + tc * 2;
            *(float2*)&po[row_a * CC + col] = make_float2(o[ni][0], o[ni][1]);
            *(float2*)&po[row_b * CC + col] = make_float2(o[ni][2], o[ni][3]);
        }

        // ---- fused combine: last-arriving CTA for this (b,qt) finishes it ----
        __threadfence();
        __syncthreads();
        if (tid == 0) {
            int old = atomicAdd(&g_done[b * QT_N + qt], 1);
            *s_flag = (old == ns - 1) ? 1 : 0;
        }
        __syncthreads();
        if (*s_flag) {
            __threadfence();
            const int s0 = (b * QT_N + qt) * MAXSUB;
            float* invl = (float*)(smem + SM_INVL);
            for (int r = tid; r < 128; r += 256) {
                float ssum = 0.0f;
                for (int u = 0; u < ns; u++) ssum += g_pl[s0 + u][r];
                invl[r] = 1.0f / ssum;
            }
            __syncthreads();
            float* dst = out + (size_t)(b * TT + qt * BQ) * CC;
#pragma unroll 2
            for (int f = tid; f < BQ * CC / 4; f += 256) {
                const int row = f >> 5;
                float4 a = *(const float4*)&g_po[s0][f * 4];
                for (int u = 1; u < ns; u++) {
                    float4 v = *(const float4*)&g_po[s0 + u][f * 4];
                    a.x += v.x; a.y += v.y; a.z += v.z; a.w += v.w;
                }
                const float inv = invl[row];
                a.x *= inv; a.y *= inv; a.z *= inv; a.w *= inv;
                *(float4*)&dst[f * 4] = a;
            }
        }

        // ---- pop next slice ----
        if (tid == 0) *s_next = atomicAdd(&g_ctr, 1);
        __syncthreads();
        slice = *s_next;
    }
}

// ---------------------------------------------------------------------------
extern "C" void kernel_launch(void* const* d_in, const int* in_sizes, int n_in,
                              void* d_out, int out_size)
{
    const float* x  = (const float*)d_in[0];
    const float* Wq = (const float*)d_in[1];
    const float* Wk = (const float*)d_in[2];
    const float* Wv = (const float*)d_in[3];
    float* out = (float*)d_out;

    cudaFuncSetAttribute(flash_attn,
                         cudaFuncAttributeMaxDynamicSharedMemorySize,
                         FLASH_SMEM);
    cudaFuncSetAttribute(qkv_proj_mma,
                         cudaFuncAttributeMaxDynamicSharedMemorySize,
                         PROJ_SMEM);

    qkv_proj_mma<<<dim3(BT / 128, 3), 256, PROJ_SMEM>>>(x, Wq, Wk, Wv);
    flash_attn<<<NCTA, 256, FLASH_SMEM>>>(out);
}